// round 16
// baseline (speedup 1.0000x reference)
#include <cuda_runtime.h>
#include <cuda_bf16.h>
#include <cuda_fp16.h>
#include <math.h>
#include <stdint.h>

#define S_LEN 4096
#define DIM   1536
#define NHEAD 12
#define HDIM  128
#define KSPLIT 3

// ---------------------------------------------------------------------------
// scratch (device globals: no cudaMalloc allowed)
// ---------------------------------------------------------------------------
__device__ float g_Q[S_LEN * DIM];
__device__ float g_K[S_LEN * DIM];

__device__ float g_U[KSPLIT * S_LEN * DIM];
__device__ float g_Sm[KSPLIT * NHEAD * S_LEN];
__device__ float g_Sl[KSPLIT * NHEAD * S_LEN];
__device__ int   g_cnt[(S_LEN / 128) * NHEAD];   // split-K completion counters

__device__ __align__(128) __half g_xf[S_LEN * DIM];
__device__ __align__(128) __half g_Af[S_LEN * DIM];
__device__ __align__(128) __half g_Qf[S_LEN * DIM];
__device__ __align__(128) __half g_Kf[S_LEN * DIM];
__device__ __align__(128) __half g_Vf[S_LEN * DIM];

__device__ __align__(128) __half g_Wqkv[3 * DIM * DIM];
__device__ __align__(128) __half g_Wof[DIM * DIM];

__device__ __forceinline__ uint32_t smem_u32(const void* p) {
    uint32_t a;
    asm("{ .reg .u64 t; cvta.to.shared.u64 t, %1; cvt.u32.u64 %0, t; }"
        : "=r"(a) : "l"(p));
    return a;
}

__device__ __forceinline__ void ldm_x4(uint32_t* r, uint32_t addr) {
    asm volatile("ldmatrix.sync.aligned.m8n8.x4.shared.b16 {%0,%1,%2,%3}, [%4];"
        : "=r"(r[0]), "=r"(r[1]), "=r"(r[2]), "=r"(r[3]) : "r"(addr));
}
__device__ __forceinline__ void ldm_x4_t(uint32_t* r, uint32_t addr) {
    asm volatile("ldmatrix.sync.aligned.m8n8.x4.trans.shared.b16 {%0,%1,%2,%3}, [%4];"
        : "=r"(r[0]), "=r"(r[1]), "=r"(r[2]), "=r"(r[3]) : "r"(addr));
}

__device__ __forceinline__ void mma_fp16(float* c, const uint32_t* a,
                                         uint32_t b0, uint32_t b1) {
    asm volatile(
        "mma.sync.aligned.m16n8k16.row.col.f32.f16.f16.f32 "
        "{%0,%1,%2,%3}, {%4,%5,%6,%7}, {%8,%9}, {%0,%1,%2,%3};"
        : "+f"(c[0]), "+f"(c[1]), "+f"(c[2]), "+f"(c[3])
        : "r"(a[0]), "r"(a[1]), "r"(a[2]), "r"(a[3]), "r"(b0), "r"(b1));
}

__device__ __forceinline__ float ex2f(float x) {
    float y;
    asm("ex2.approx.ftz.f32 %0, %1;" : "=f"(y) : "f"(x));
    return y;
}
__device__ __forceinline__ uint32_t ex2_h2(uint32_t x) {
    uint32_t y;
    asm("ex2.approx.f16x2 %0, %1;" : "=r"(y) : "r"(x));
    return y;
}

#define CP_ASYNC16(saddr, gptr) \
    asm volatile("cp.async.cg.shared.global [%0], [%1], 16;" :: "r"(saddr), "l"(gptr))
#define CP_COMMIT()  asm volatile("cp.async.commit_group;" ::: "memory")
#define CP_WAIT1()   asm volatile("cp.async.wait_group 1;" ::: "memory")
#define CP_WAIT0()   asm volatile("cp.async.wait_group 0;" ::: "memory")

#define K2C 0.1275025621249438f   // (1/sqrt(128)) * log2(e)
#define ONES_H2 0x3C003C00u       // fp16 {1.0, 1.0}

// ---------------------------------------------------------------------------
// merged fp32 -> fp16 conversion, grid-stride
// ---------------------------------------------------------------------------
#define X4 (S_LEN * DIM / 4)
#define W4 (DIM * DIM / 4)
#define TOT4 (X4 + 4 * W4)

__global__ void convert_all_kernel(const float* __restrict__ x,
                                   const float* __restrict__ Wq,
                                   const float* __restrict__ Wk,
                                   const float* __restrict__ Wv,
                                   const float* __restrict__ Wo,
                                   __half* __restrict__ xf,
                                   __half* __restrict__ wqkv,
                                   __half* __restrict__ wof) {
    const int stride = gridDim.x * blockDim.x;
    for (int i = blockIdx.x * blockDim.x + threadIdx.x; i < TOT4; i += stride) {
        const float* src;
        __half* dst;
        int off;
        if (i < X4)               { src = x;  dst = xf;   off = i; }
        else if (i < X4 + W4)     { src = Wq; dst = wqkv; off = i - X4; }
        else if (i < X4 + 2 * W4) { src = Wk; dst = wqkv + (size_t)DIM * DIM;     off = i - X4 - W4; }
        else if (i < X4 + 3 * W4) { src = Wv; dst = wqkv + 2 * (size_t)DIM * DIM; off = i - X4 - 2 * W4; }
        else                      { src = Wo; dst = wof;  off = i - X4 - 3 * W4; }
        float4 v = ((const float4*)src)[off];
        __half2 a = __floats2half2_rn(v.x, v.y);
        __half2 b = __floats2half2_rn(v.z, v.w);
        uint2 o = { *(uint32_t*)&a, *(uint32_t*)&b };
        *(uint2*)(dst + 4 * (size_t)off) = o;
    }
}

// ---------------------------------------------------------------------------
// shared GEMM tiling constants
// ---------------------------------------------------------------------------
#define GBM 128
#define GBN 128
#define GBK 32
#define G_NC (DIM / GBK)
#define G_ROWB 80
#define G_TILEB (128 * G_ROWB)
#define G1_STAGEB (2 * G_TILEB)
#define G1_SMEM (2 * G1_STAGEB)   // 40960

// ---------------------------------------------------------------------------
// Fused QKV GEMM (round-15: 4 warps, warp tile 64x64)
// ---------------------------------------------------------------------------
__global__ __launch_bounds__(128)
void gemm_qkv_kernel(const __half* __restrict__ A,
                     const __half* __restrict__ Wqkv,
                     const float* __restrict__ bq,
                     const float* __restrict__ bk,
                     const float* __restrict__ bv,
                     float* __restrict__ Cq,
                     float* __restrict__ Ck,
                     __half* __restrict__ Cv) {
    extern __shared__ char smem[];
    const uint32_t sbase = smem_u32(smem);
    const int tid  = threadIdx.x;
    const int wid  = tid >> 5;
    const int lane = tid & 31;
    const int bm   = blockIdx.y * GBM;
    const int mat  = blockIdx.x / 12;
    const int bn   = (blockIdx.x % 12) * GBN;
    const int warp_m = wid & 1;
    const int warp_n = wid >> 1;

    const float* biasv[3] = { bq, bk, bv };
    const float* bias = biasv[mat];

    const __half* basep[2] = {
        A + (size_t)bm * DIM,
        Wqkv + (size_t)blockIdx.x * GBN * DIM };
    const int cp_row = tid >> 2;
    const int cp_c4  = tid & 3;

    auto copy_chunk = [&](int c, uint32_t stage) {
        #pragma unroll
        for (int t = 0; t < 2; t++) {
            #pragma unroll
            for (int half = 0; half < 4; half++) {
                const int row = cp_row + half * 32;
                const __half* g = basep[t] + (size_t)row * DIM + c * GBK + cp_c4 * 8;
                CP_ASYNC16(stage + t * G_TILEB + row * G_ROWB + cp_c4 * 16, g);
            }
        }
    };

    float acc[4][8][4] = {};
    copy_chunk(0, sbase);
    CP_COMMIT();

    for (int c = 0; c < G_NC; c++) {
        __syncthreads();
        if (c + 1 < G_NC) {
            copy_chunk(c + 1, sbase + ((c + 1) & 1) * G1_STAGEB);
            CP_COMMIT();
            CP_WAIT1();
        } else {
            CP_WAIT0();
        }
        __syncthreads();

        const uint32_t st = sbase + (c & 1) * G1_STAGEB;
        const uint32_t aT = st;
        const uint32_t bT = st + G_TILEB;

        #pragma unroll
        for (int kk = 0; kk < GBK; kk += 16) {
            uint32_t bf[16];
            #pragma unroll
            for (int nt2 = 0; nt2 < 4; nt2++) {
                const int n  = warp_n * 64 + nt2 * 16 + (lane & 7) + ((lane >> 4) << 3);
                const int kc = kk + (((lane >> 3) & 1) << 3);
                ldm_x4(&bf[nt2 * 4], bT + n * G_ROWB + kc * 2);
            }
            uint32_t af[16];
            {
                const int rbase = warp_m * 64 + (lane & 15);
                const int kc    = kk + ((lane >> 4) << 3);
                #pragma unroll
                for (int mt = 0; mt < 4; mt++)
                    ldm_x4(&af[mt * 4], aT + (rbase + mt * 16) * G_ROWB + kc * 2);
            }
            #pragma unroll
            for (int mt = 0; mt < 4; mt++)
                #pragma unroll
                for (int nt = 0; nt < 8; nt++) {
                    const int bi = (nt >> 1) * 4 + (nt & 1) * 2;
                    mma_fp16(acc[mt][nt], &af[mt * 4], bf[bi], bf[bi + 1]);
                }
        }
    }

    if (mat < 2) {
        float* C = mat ? Ck : Cq;
        #pragma unroll
        for (int mt = 0; mt < 4; mt++) {
            const int row0 = bm + warp_m * 64 + mt * 16 + (lane >> 2);
            #pragma unroll
            for (int nt = 0; nt < 8; nt++) {
                const int col = bn + warp_n * 64 + nt * 8 + ((lane & 3) << 1);
                const float b0 = bias[col], b1 = bias[col + 1];
                float2 v0 = { acc[mt][nt][0] + b0, acc[mt][nt][1] + b1 };
                float2 v1 = { acc[mt][nt][2] + b0, acc[mt][nt][3] + b1 };
                *(float2*)&C[(size_t)row0 * DIM + col]       = v0;
                *(float2*)&C[(size_t)(row0 + 8) * DIM + col] = v1;
            }
        }
    } else {
        #pragma unroll
        for (int mt = 0; mt < 4; mt++) {
            const int row0 = bm + warp_m * 64 + mt * 16 + (lane >> 2);
            #pragma unroll
            for (int nt = 0; nt < 8; nt++) {
                const int col = bn + warp_n * 64 + nt * 8 + ((lane & 3) << 1);
                const float b0 = bias[col], b1 = bias[col + 1];
                __half2 v0 = __floats2half2_rn(acc[mt][nt][0] + b0, acc[mt][nt][1] + b1);
                __half2 v1 = __floats2half2_rn(acc[mt][nt][2] + b0, acc[mt][nt][3] + b1);
                *(uint32_t*)&Cv[(size_t)row0 * DIM + col]       = *(uint32_t*)&v0;
                *(uint32_t*)&Cv[(size_t)(row0 + 8) * DIM + col] = *(uint32_t*)&v1;
            }
        }
    }
}

// ---------------------------------------------------------------------------
// Wo GEMM: REVERTED to verified round-12 128x128 2-stage
// ---------------------------------------------------------------------------
__global__ __launch_bounds__(256)
void gemm1_kernel(const __half* __restrict__ A,
                  const __half* __restrict__ B,
                  const float* __restrict__ bias,
                  float* __restrict__ C) {
    extern __shared__ char smem[];
    const uint32_t sbase = smem_u32(smem);
    const int tid  = threadIdx.x;
    const int wid  = tid >> 5;
    const int lane = tid & 31;
    const int bm   = blockIdx.y * GBM;
    const int bn   = blockIdx.x * GBN;
    const int warp_m = wid & 1;
    const int warp_n = wid >> 1;

    const __half* basep[2] = { A + (size_t)bm * DIM, B + (size_t)bn * DIM };
    const int cp_row[2] = { tid >> 2, (tid + 256) >> 2 };
    const int cp_c4     = tid & 3;

    auto copy_chunk = [&](int c, uint32_t stage) {
        #pragma unroll
        for (int t = 0; t < 2; t++) {
            #pragma unroll
            for (int half = 0; half < 2; half++) {
                const int row = cp_row[half];
                const __half* g = basep[t] + (size_t)row * DIM + c * GBK + cp_c4 * 8;
                CP_ASYNC16(stage + t * G_TILEB + row * G_ROWB + cp_c4 * 16, g);
            }
        }
    };

    float acc[4][4][4] = {};
    copy_chunk(0, sbase);
    CP_COMMIT();

    for (int c = 0; c < G_NC; c++) {
        __syncthreads();
        if (c + 1 < G_NC) {
            copy_chunk(c + 1, sbase + ((c + 1) & 1) * G1_STAGEB);
            CP_COMMIT();
            CP_WAIT1();
        } else {
            CP_WAIT0();
        }
        __syncthreads();

        const uint32_t st = sbase + (c & 1) * G1_STAGEB;
        const uint32_t aT = st;
        const uint32_t bT = st + G_TILEB;

        #pragma unroll
        for (int kk = 0; kk < GBK; kk += 16) {
            uint32_t bf[8];
            #pragma unroll
            for (int nt2 = 0; nt2 < 2; nt2++) {
                const int n  = warp_n * 32 + nt2 * 16 + (lane & 7) + ((lane >> 4) << 3);
                const int kc = kk + (((lane >> 3) & 1) << 3);
                ldm_x4(&bf[nt2 * 4], bT + n * G_ROWB + kc * 2);
            }
            uint32_t af[16];
            {
                const int rbase = warp_m * 64 + (lane & 15);
                const int kc    = kk + ((lane >> 4) << 3);
                #pragma unroll
                for (int mt = 0; mt < 4; mt++)
                    ldm_x4(&af[mt * 4], aT + (rbase + mt * 16) * G_ROWB + kc * 2);
            }
            #pragma unroll
            for (int mt = 0; mt < 4; mt++)
                #pragma unroll
                for (int nt = 0; nt < 4; nt++) {
                    const int bi = (nt >> 1) * 4 + (nt & 1) * 2;
                    mma_fp16(acc[mt][nt], &af[mt * 4], bf[bi], bf[bi + 1]);
                }
        }
    }

    #pragma unroll
    for (int mt = 0; mt < 4; mt++) {
        const int row0 = bm + warp_m * 64 + mt * 16 + (lane >> 2);
        #pragma unroll
        for (int nt = 0; nt < 4; nt++) {
            const int col = bn + warp_n * 32 + nt * 8 + ((lane & 3) << 1);
            const float b0 = bias[col], b1 = bias[col + 1];
            float2 v0 = { acc[mt][nt][0] + b0, acc[mt][nt][1] + b1 };
            float2 v1 = { acc[mt][nt][2] + b0, acc[mt][nt][3] + b1 };
            *(float2*)&C[(size_t)row0 * DIM + col]       = v0;
            *(float2*)&C[(size_t)(row0 + 8) * DIM + col] = v1;
        }
    }
}

// ---------------------------------------------------------------------------
// Fused RMSNorm + RoPE: REVERTED to verified round-12 scalar version
// ---------------------------------------------------------------------------
__global__ void rmsnorm_rope_kernel(const float* __restrict__ Xq,
                                    const float* __restrict__ Xk,
                                    const float* __restrict__ gqv,
                                    const float* __restrict__ gkv,
                                    const float* __restrict__ fc,
                                    const float* __restrict__ fs,
                                    __half* __restrict__ Oq,
                                    __half* __restrict__ Ok) {
    const int s = blockIdx.x;
    const int which = blockIdx.y;
    const float* X = which ? Xk : Xq;
    const float* g = which ? gkv : gqv;
    __half* O = which ? Ok : Oq;

    __shared__ float buf[DIM];
    __shared__ float red[8];
    __shared__ float s_scale;

    const float* row = X + (size_t)s * DIM;

    float ss = 0.f;
    for (int i = threadIdx.x; i < DIM; i += blockDim.x) {
        float v = row[i];
        buf[i] = v;
        ss += v * v;
    }
    #pragma unroll
    for (int o = 16; o > 0; o >>= 1) ss += __shfl_xor_sync(0xFFFFFFFFu, ss, o);
    if ((threadIdx.x & 31) == 0) red[threadIdx.x >> 5] = ss;
    __syncthreads();
    if (threadIdx.x == 0) {
        float t = 0.f;
        #pragma unroll
        for (int w = 0; w < 8; w++) t += red[w];
        s_scale = rsqrtf(t / (float)DIM + 1e-6f);
    }
    __syncthreads();
    const float scale = s_scale;

    const float* fcs = fc + (size_t)s * HDIM;
    const float* fss = fs + (size_t)s * HDIM;

    for (int i = threadIdx.x; i < DIM; i += blockDim.x) {
        int j = i & (HDIM - 1);
        float v = buf[i] * scale * g[i];
        float out;
        if (j < HDIM / 2) {
            float other = buf[i + HDIM / 2] * scale * g[i + HDIM / 2];
            out = v * fcs[j] - other * fss[j];
        } else {
            float other = buf[i - HDIM / 2] * scale * g[i - HDIM / 2];
            out = v * fcs[j] + other * fss[j];
        }
        O[(size_t)s * DIM + i] = __float2half(out);
    }
}

// ---------------------------------------------------------------------------
// Flash attention (round-14/15 verified) + FUSED split-K combine in last CTA
// ---------------------------------------------------------------------------
#define A_PITCH 272
#define Q_TILEB (128 * A_PITCH)
#define KV_TILEB (64 * A_PITCH)
#define OFF_KV  Q_TILEB
#define ATT_SMEM (OFF_KV + 4 * KV_TILEB)   // 104448

__global__ __launch_bounds__(128)
void attn_mma_kernel(const __half* __restrict__ Q_g,
                     const __half* __restrict__ K_g,
                     const __half* __restrict__ V_g,
                     float* __restrict__ U,
                     float* __restrict__ Sm,
                     float* __restrict__ Sl,
                     int* __restrict__ cnt,
                     __half* __restrict__ Af) {
    extern __shared__ char smem[];
    const uint32_t sb = smem_u32(smem);
    const int tid  = threadIdx.x;
    const int wid  = tid >> 5;
    const int lane = tid & 31;
    const int h    = blockIdx.y;
    const int q0   = blockIdx.x * 128;
    const int split = blockIdx.z;
    const int kt0    = split == 0 ? 0 : (split == 1 ? 22 : 43);
    const int ntiles = split == 0 ? 22 : 21;

    const uint32_t sQ = sb;

    #pragma unroll
    for (int i = 0; i < 16; i++) {
        int cid = i * 128 + tid;
        int row = cid >> 4, c = cid & 15;
        const __half* gp = Q_g + (size_t)(q0 + row) * DIM + h * HDIM + c * 8;
        CP_ASYNC16(sQ + row * A_PITCH + c * 16, gp);
    }
    const __half* kvsrc[2] = { K_g, V_g };
    auto load_stage = [&](int kt, int s) {
        uint32_t stb = sb + OFF_KV + s * 2 * KV_TILEB;
        #pragma unroll
        for (int i = 0; i < 16; i++) {
            int cid = i * 128 + tid;
            int tile = cid >> 10, row = (cid >> 4) & 63, c = cid & 15;
            const __half* gp = kvsrc[tile] + (size_t)(kt * 64 + row) * DIM + h * HDIM + c * 8;
            CP_ASYNC16(stb + tile * KV_TILEB + row * A_PITCH + c * 16, gp);
        }
    };
    load_stage(kt0, 0);
    CP_COMMIT();
    load_stage(kt0 + 1, 1);
    CP_COMMIT();

    float m00 = -1e30f, m01 = -1e30f, m10 = -1e30f, m11 = -1e30f;
    float oacc[2][16][4] = {};
    float lacc[2][4] = {};

    const int rb = wid * 32 + (lane & 15);

    for (int t = 0; t < ntiles; t++) {
        if (t < ntiles - 1) CP_WAIT1(); else CP_WAIT0();
        __syncthreads();
        const uint32_t st = sb + OFF_KV + (t & 1) * 2 * KV_TILEB;
        const uint32_t sK = st;
        const uint32_t sV = st + KV_TILEB;

        float sacc[2][8][4] = {};
        #pragma unroll
        for (int kk = 0; kk < 8; kk++) {
            uint32_t aq0[4], aq1[4];
            const int kc = kk * 16 + ((lane >> 4) << 3);
            ldm_x4(aq0, sQ + rb * A_PITCH + kc * 2);
            ldm_x4(aq1, sQ + (rb + 16) * A_PITCH + kc * 2);
            const int kc2 = kk * 16 + (((lane >> 3) & 1) << 3);
            #pragma unroll
            for (int half = 0; half < 2; half++) {
                uint32_t bk[8];
                const int nr = half * 32 + (lane & 7) + ((lane >> 4) << 3);
                ldm_x4(bk,     sK + nr * A_PITCH + kc2 * 2);
                ldm_x4(bk + 4, sK + (nr + 16) * A_PITCH + kc2 * 2);
                #pragma unroll
                for (int j = 0; j < 4; j++) {
                    mma_fp16(sacc[0][half * 4 + j], aq0, bk[j * 2], bk[j * 2 + 1]);
                    mma_fp16(sacc[1][half * 4 + j], aq1, bk[j * 2], bk[j * 2 + 1]);
                }
            }
        }

        uint32_t pA[2][8], pB[2][8];
        float a00, a01, a10, a11;
        #pragma unroll
        for (int mt = 0; mt < 2; mt++) {
            float mx0 = -1e30f, mx1 = -1e30f;
            #pragma unroll
            for (int nt = 0; nt < 8; nt++) {
                mx0 = fmaxf(mx0, fmaxf(sacc[mt][nt][0], sacc[mt][nt][1]));
                mx1 = fmaxf(mx1, fmaxf(sacc[mt][nt][2], sacc[mt][nt][3]));
            }
            mx0 = fmaxf(mx0, __shfl_xor_sync(0xFFFFFFFFu, mx0, 1));
            mx0 = fmaxf(mx0, __shfl_xor_sync(0xFFFFFFFFu, mx0, 2));
            mx1 = fmaxf(mx1, __shfl_xor_sync(0xFFFFFFFFu, mx1, 1));
            mx1 = fmaxf(mx1, __shfl_xor_sync(0xFFFFFFFFu, mx1, 2));
            float& m0r = mt ? m10 : m00;
            float& m1r = mt ? m11 : m01;
            const float mn0 = fmaxf(m0r, mx0);
            const float mn1 = fmaxf(m1r, mx1);
            const float a0 = ex2f((m0r - mn0) * K2C);
            const float a1 = ex2f((m1r - mn1) * K2C);
            m0r = mn0; m1r = mn1;
            const float mnK0 = mn0 * K2C;
            const float mnK1 = mn1 * K2C;
            #pragma unroll
            for (int nt = 0; nt < 8; nt++) {
                float e0 = fmaf(sacc[mt][nt][0], K2C, -mnK0);
                float e1 = fmaf(sacc[mt][nt][1], K2C, -mnK0);
                float e2 = fmaf(sacc[mt][nt][2], K2C, -mnK1);
                float e3 = fmaf(sacc[mt][nt][3], K2C, -mnK1);
                __half2 hA = __floats2half2_rn(e0, e1);
                __half2 hB = __floats2half2_rn(e2, e3);
                pA[mt][nt] = ex2_h2(*(uint32_t*)&hA);
                pB[mt][nt] = ex2_h2(*(uint32_t*)&hB);
            }
            if (mt) { a10 = a0; a11 = a1; } else { a00 = a0; a01 = a1; }
        }

        const bool noscale = (a00 == 1.f) & (a01 == 1.f) & (a10 == 1.f) & (a11 == 1.f);
        if (!__all_sync(0xFFFFFFFFu, noscale)) {
            #pragma unroll
            for (int nt = 0; nt < 16; nt++) {
                oacc[0][nt][0] *= a00; oacc[0][nt][1] *= a00;
                oacc[0][nt][2] *= a01; oacc[0][nt][3] *= a01;
                oacc[1][nt][0] *= a10; oacc[1][nt][1] *= a10;
                oacc[1][nt][2] *= a11; oacc[1][nt][3] *= a11;
            }
            lacc[0][0] *= a00; lacc[0][1] *= a00;
            lacc[0][2] *= a01; lacc[0][3] *= a01;
            lacc[1][0] *= a10; lacc[1][1] *= a10;
            lacc[1][2] *= a11; lacc[1][3] *= a11;
        }

        #pragma unroll
        for (int kk = 0; kk < 4; kk++) {
            uint32_t ap0[4] = { pA[0][2 * kk], pB[0][2 * kk],
                                pA[0][2 * kk + 1], pB[0][2 * kk + 1] };
            uint32_t ap1[4] = { pA[1][2 * kk], pB[1][2 * kk],
                                pA[1][2 * kk + 1], pB[1][2 * kk + 1] };
            const int vr = kk * 16 + (lane & 7) + (((lane >> 3) & 1) << 3);
            #pragma unroll
            for (int q = 0; q < 4; q++) {
                uint32_t bv[8];
                const int vc = q * 32 + ((lane >> 4) << 3);
                ldm_x4_t(bv,     sV + vr * A_PITCH + vc * 2);
                ldm_x4_t(bv + 4, sV + vr * A_PITCH + (vc + 16) * 2);
                #pragma unroll
                for (int j = 0; j < 4; j++) {
                    mma_fp16(oacc[0][q * 4 + j], ap0, bv[j * 2], bv[j * 2 + 1]);
                    mma_fp16(oacc[1][q * 4 + j], ap1, bv[j * 2], bv[j * 2 + 1]);
                }
            }
            mma_fp16(lacc[0], ap0, ONES_H2, ONES_H2);
            mma_fp16(lacc[1], ap1, ONES_H2, ONES_H2);
        }
        __syncthreads();

        if (t + 2 < ntiles) {
            load_stage(kt0 + t + 2, t & 1);
            CP_COMMIT();
        }
    }

    // ---- epilogue: write partial numerator U (fp32) + stats ----
    #pragma unroll
    for (int mt = 0; mt < 2; mt++) {
        const int r = wid * 32 + mt * 16 + (lane >> 2);
        const int row0 = q0 + r, row1 = q0 + r + 8;
        const float m0 = mt ? m10 : m00;
        const float m1 = mt ? m11 : m01;
        if ((lane & 3) == 0) {
            const int sbp = (split * NHEAD + h) * S_LEN;
            Sm[sbp + row0] = m0; Sl[sbp + row0] = lacc[mt][0];
            Sm[sbp + row1] = m1; Sl[sbp + row1] = lacc[mt][2];
        }
        float* Ub = U + (size_t)split * S_LEN * DIM;
        const size_t gr0 = (size_t)row0 * DIM;
        const size_t gr1 = (size_t)row1 * DIM;
        #pragma unroll
        for (int nt = 0; nt < 16; nt++) {
            const int col = h * HDIM + nt * 8 + ((lane & 3) << 1);
            float2 u0 = { oacc[mt][nt][0], oacc[mt][nt][1] };
            float2 u1 = { oacc[mt][nt][2], oacc[mt][nt][3] };
            *(float2*)&Ub[gr0 + col] = u0;
            *(float2*)&Ub[gr1 + col] = u1;
        }
    }

    // ---- fused split-K combine: last CTA for this (q-block, head) ----
    __shared__ int s_last;
    __threadfence();   // release U/Sm/Sl writes
    if (tid == 0) {
        int old = atomicAdd(&cnt[blockIdx.x * NHEAD + h], 1);
        s_last = (old == KSPLIT - 1) ? 1 : 0;
    }
    __syncthreads();
    if (s_last) {
        __threadfence();   // acquire other splits' writes
        const size_t stride = (size_t)S_LEN * DIM;
        #pragma unroll 1
        for (int it = 0; it < 16; it++) {
            const int idx = it * 128 + tid;     // 0..2047
            const int r   = idx >> 4;           // 0..127
            const int cc  = idx & 15;           // 0..15 (8 cols each)
            const int row = q0 + r;
            const int s0 = h * S_LEN + row;
            const int s1 = s0 + NHEAD * S_LEN;
            const int s2 = s1 + NHEAD * S_LEN;
            const float m0 = Sm[s0], m1 = Sm[s1], m2 = Sm[s2];
            const float M = fmaxf(m0, fmaxf(m1, m2));
            const float w0 = ex2f((m0 - M) * K2C);
            const float w1 = ex2f((m1 - M) * K2C);
            const float w2 = ex2f((m2 - M) * K2C);
            const float inv = 1.f / (Sl[s0] * w0 + Sl[s1] * w1 + Sl[s2] * w2);

            const size_t e = (size_t)row * DIM + h * HDIM + cc * 8;
            float4 a0 = *(const float4*)&U[e];
            float4 a1 = *(const float4*)&U[e + 4];
            float4 b0 = *(const float4*)&U[stride + e];
            float4 b1 = *(const float4*)&U[stride + e + 4];
            float4 c0 = *(const float4*)&U[2 * stride + e];
            float4 c1 = *(const float4*)&U[2 * stride + e + 4];
            float o0 = (a0.x * w0 + b0.x * w1 + c0.x * w2) * inv;
            float o1 = (a0.y * w0 + b0.y * w1 + c0.y * w2) * inv;
            float o2 = (a0.z * w0 + b0.z * w1 + c0.z * w2) * inv;
            float o3 = (a0.w * w0 + b0.w * w1 + c0.w * w2) * inv;
            float o4 = (a1.x * w0 + b1.x * w1 + c1.x * w2) * inv;
            float o5 = (a1.y * w0 + b1.y * w1 + c1.y * w2) * inv;
            float o6 = (a1.z * w0 + b1.z * w1 + c1.z * w2) * inv;
            float o7 = (a1.w * w0 + b1.w * w1 + c1.w * w2) * inv;
            __half2 p0 = __floats2half2_rn(o0, o1);
            __half2 p1 = __floats2half2_rn(o2, o3);
            __half2 p2 = __floats2half2_rn(o4, o5);
            __half2 p3 = __floats2half2_rn(o6, o7);
            uint4 o = { *(uint32_t*)&p0, *(uint32_t*)&p1,
                        *(uint32_t*)&p2, *(uint32_t*)&p3 };
            *(uint4*)&Af[e] = o;
        }
    }
}

// ---------------------------------------------------------------------------
extern "C" void kernel_launch(void* const* d_in, const int* in_sizes, int n_in,
                              void* d_out, int out_size) {
    const float* x   = (const float*)d_in[0];
    const float* fc  = (const float*)d_in[1];
    const float* fs  = (const float*)d_in[2];
    const float* Wq  = (const float*)d_in[3];
    const float* bq  = (const float*)d_in[4];
    const float* Wk  = (const float*)d_in[5];
    const float* bk  = (const float*)d_in[6];
    const float* Wv  = (const float*)d_in[7];
    const float* bv  = (const float*)d_in[8];
    const float* Wo  = (const float*)d_in[9];
    const float* bo  = (const float*)d_in[10];
    const float* gq  = (const float*)d_in[11];
    const float* gk  = (const float*)d_in[12];
    float* out = (float*)d_out;

    float *dQ, *dK, *dU, *dSm, *dSl;
    int* dCnt;
    cudaGetSymbolAddress((void**)&dQ, g_Q);
    cudaGetSymbolAddress((void**)&dK, g_K);
    cudaGetSymbolAddress((void**)&dU, g_U);
    cudaGetSymbolAddress((void**)&dSm, g_Sm);
    cudaGetSymbolAddress((void**)&dSl, g_Sl);
    cudaGetSymbolAddress((void**)&dCnt, g_cnt);
    __half *xf, *af, *qf, *kf, *vf, *wqkv, *wof;
    cudaGetSymbolAddress((void**)&xf, g_xf);
    cudaGetSymbolAddress((void**)&af, g_Af);
    cudaGetSymbolAddress((void**)&qf, g_Qf);
    cudaGetSymbolAddress((void**)&kf, g_Kf);
    cudaGetSymbolAddress((void**)&vf, g_Vf);
    cudaGetSymbolAddress((void**)&wqkv, g_Wqkv);
    cudaGetSymbolAddress((void**)&wof, g_Wof);

    cudaMemsetAsync(dCnt, 0, (S_LEN / 128) * NHEAD * sizeof(int));
    convert_all_kernel<<<2048, 256>>>(x, Wq, Wk, Wv, Wo, xf, wqkv, wof);

    cudaFuncSetAttribute(gemm_qkv_kernel, cudaFuncAttributeMaxDynamicSharedMemorySize, G1_SMEM);
    cudaFuncSetAttribute(gemm1_kernel, cudaFuncAttributeMaxDynamicSharedMemorySize, G1_SMEM);

    dim3 gqkv(3 * DIM / GBN, S_LEN / GBM);
    gemm_qkv_kernel<<<gqkv, 128, G1_SMEM>>>(xf, wqkv, bq, bk, bv, dQ, dK, vf);

    dim3 rgrid(S_LEN, 2);
    rmsnorm_rope_kernel<<<rgrid, 256>>>(dQ, dK, gq, gk, fc, fs, qf, kf);

    cudaFuncSetAttribute(attn_mma_kernel, cudaFuncAttributeMaxDynamicSharedMemorySize, ATT_SMEM);
    dim3 agrid(S_LEN / 128, NHEAD, KSPLIT);
    attn_mma_kernel<<<agrid, 128, ATT_SMEM>>>(qf, kf, vf, dU, dSm, dSl, dCnt, af);

    dim3 ggrid(DIM / GBN, S_LEN / GBM);
    gemm1_kernel<<<ggrid, 256, G1_SMEM>>>(af, wof, bo, out);
}

// round 17
// speedup vs baseline: 1.0226x; 1.0226x over previous
#include <cuda_runtime.h>
#include <cuda_bf16.h>
#include <cuda_fp16.h>
#include <math.h>
#include <stdint.h>

#define S_LEN 4096
#define DIM   1536
#define NHEAD 12
#define HDIM  128
#define KSPLIT 3

// ---------------------------------------------------------------------------
// scratch (device globals: no cudaMalloc allowed)
// ---------------------------------------------------------------------------
__device__ float g_Q[S_LEN * DIM];
__device__ float g_K[S_LEN * DIM];

__device__ float g_U[KSPLIT * S_LEN * DIM];
__device__ float g_Sm[KSPLIT * NHEAD * S_LEN];
__device__ float g_Sl[KSPLIT * NHEAD * S_LEN];

__device__ __align__(128) __half g_xf[S_LEN * DIM];
__device__ __align__(128) __half g_Af[S_LEN * DIM];
__device__ __align__(128) __half g_Qf[S_LEN * DIM];
__device__ __align__(128) __half g_Kf[S_LEN * DIM];
__device__ __align__(128) __half g_Vf[S_LEN * DIM];

__device__ __align__(128) __half g_Wqkv[3 * DIM * DIM];
__device__ __align__(128) __half g_Wof[DIM * DIM];

__device__ __forceinline__ uint32_t smem_u32(const void* p) {
    uint32_t a;
    asm("{ .reg .u64 t; cvta.to.shared.u64 t, %1; cvt.u32.u64 %0, t; }"
        : "=r"(a) : "l"(p));
    return a;
}

__device__ __forceinline__ void ldm_x4(uint32_t* r, uint32_t addr) {
    asm volatile("ldmatrix.sync.aligned.m8n8.x4.shared.b16 {%0,%1,%2,%3}, [%4];"
        : "=r"(r[0]), "=r"(r[1]), "=r"(r[2]), "=r"(r[3]) : "r"(addr));
}
__device__ __forceinline__ void ldm_x4_t(uint32_t* r, uint32_t addr) {
    asm volatile("ldmatrix.sync.aligned.m8n8.x4.trans.shared.b16 {%0,%1,%2,%3}, [%4];"
        : "=r"(r[0]), "=r"(r[1]), "=r"(r[2]), "=r"(r[3]) : "r"(addr));
}

__device__ __forceinline__ void mma_fp16(float* c, const uint32_t* a,
                                         uint32_t b0, uint32_t b1) {
    asm volatile(
        "mma.sync.aligned.m16n8k16.row.col.f32.f16.f16.f32 "
        "{%0,%1,%2,%3}, {%4,%5,%6,%7}, {%8,%9}, {%0,%1,%2,%3};"
        : "+f"(c[0]), "+f"(c[1]), "+f"(c[2]), "+f"(c[3])
        : "r"(a[0]), "r"(a[1]), "r"(a[2]), "r"(a[3]), "r"(b0), "r"(b1));
}

__device__ __forceinline__ float ex2f(float x) {
    float y;
    asm("ex2.approx.ftz.f32 %0, %1;" : "=f"(y) : "f"(x));
    return y;
}
__device__ __forceinline__ uint32_t ex2_h2(uint32_t x) {
    uint32_t y;
    asm("ex2.approx.f16x2 %0, %1;" : "=r"(y) : "r"(x));
    return y;
}

#define CP_ASYNC16(saddr, gptr) \
    asm volatile("cp.async.cg.shared.global [%0], [%1], 16;" :: "r"(saddr), "l"(gptr))
#define CP_COMMIT()  asm volatile("cp.async.commit_group;" ::: "memory")
#define CP_WAIT1()   asm volatile("cp.async.wait_group 1;" ::: "memory")
#define CP_WAIT0()   asm volatile("cp.async.wait_group 0;" ::: "memory")

#define K2C 0.1275025621249438f   // (1/sqrt(128)) * log2(e)
#define ONES_H2 0x3C003C00u       // fp16 {1.0, 1.0}

// ---------------------------------------------------------------------------
// merged fp32 -> fp16 conversion, grid-stride
// ---------------------------------------------------------------------------
#define X4 (S_LEN * DIM / 4)
#define W4 (DIM * DIM / 4)
#define TOT4 (X4 + 4 * W4)

__global__ void convert_all_kernel(const float* __restrict__ x,
                                   const float* __restrict__ Wq,
                                   const float* __restrict__ Wk,
                                   const float* __restrict__ Wv,
                                   const float* __restrict__ Wo,
                                   __half* __restrict__ xf,
                                   __half* __restrict__ wqkv,
                                   __half* __restrict__ wof) {
    const int stride = gridDim.x * blockDim.x;
    for (int i = blockIdx.x * blockDim.x + threadIdx.x; i < TOT4; i += stride) {
        const float* src;
        __half* dst;
        int off;
        if (i < X4)               { src = x;  dst = xf;   off = i; }
        else if (i < X4 + W4)     { src = Wq; dst = wqkv; off = i - X4; }
        else if (i < X4 + 2 * W4) { src = Wk; dst = wqkv + (size_t)DIM * DIM;     off = i - X4 - W4; }
        else if (i < X4 + 3 * W4) { src = Wv; dst = wqkv + 2 * (size_t)DIM * DIM; off = i - X4 - 2 * W4; }
        else                      { src = Wo; dst = wof;  off = i - X4 - 3 * W4; }
        float4 v = ((const float4*)src)[off];
        __half2 a = __floats2half2_rn(v.x, v.y);
        __half2 b = __floats2half2_rn(v.z, v.w);
        uint2 o = { *(uint32_t*)&a, *(uint32_t*)&b };
        *(uint2*)(dst + 4 * (size_t)off) = o;
    }
}

// ---------------------------------------------------------------------------
// shared GEMM tiling constants
// ---------------------------------------------------------------------------
#define GBM 128
#define GBN 128
#define GBK 32
#define G_NC (DIM / GBK)
#define G_ROWB 80
#define G_TILEB (128 * G_ROWB)
#define G1_STAGEB (2 * G_TILEB)
#define G1_SMEM (2 * G1_STAGEB)   // 40960

// ---------------------------------------------------------------------------
// Fused QKV GEMM (round-15: 4 warps, warp tile 64x64)
// ---------------------------------------------------------------------------
__global__ __launch_bounds__(128)
void gemm_qkv_kernel(const __half* __restrict__ A,
                     const __half* __restrict__ Wqkv,
                     const float* __restrict__ bq,
                     const float* __restrict__ bk,
                     const float* __restrict__ bv,
                     float* __restrict__ Cq,
                     float* __restrict__ Ck,
                     __half* __restrict__ Cv) {
    extern __shared__ char smem[];
    const uint32_t sbase = smem_u32(smem);
    const int tid  = threadIdx.x;
    const int wid  = tid >> 5;
    const int lane = tid & 31;
    const int bm   = blockIdx.y * GBM;
    const int mat  = blockIdx.x / 12;
    const int bn   = (blockIdx.x % 12) * GBN;
    const int warp_m = wid & 1;
    const int warp_n = wid >> 1;

    const float* biasv[3] = { bq, bk, bv };
    const float* bias = biasv[mat];

    const __half* basep[2] = {
        A + (size_t)bm * DIM,
        Wqkv + (size_t)blockIdx.x * GBN * DIM };
    const int cp_row = tid >> 2;
    const int cp_c4  = tid & 3;

    auto copy_chunk = [&](int c, uint32_t stage) {
        #pragma unroll
        for (int t = 0; t < 2; t++) {
            #pragma unroll
            for (int half = 0; half < 4; half++) {
                const int row = cp_row + half * 32;
                const __half* g = basep[t] + (size_t)row * DIM + c * GBK + cp_c4 * 8;
                CP_ASYNC16(stage + t * G_TILEB + row * G_ROWB + cp_c4 * 16, g);
            }
        }
    };

    float acc[4][8][4] = {};
    copy_chunk(0, sbase);
    CP_COMMIT();

    for (int c = 0; c < G_NC; c++) {
        __syncthreads();
        if (c + 1 < G_NC) {
            copy_chunk(c + 1, sbase + ((c + 1) & 1) * G1_STAGEB);
            CP_COMMIT();
            CP_WAIT1();
        } else {
            CP_WAIT0();
        }
        __syncthreads();

        const uint32_t st = sbase + (c & 1) * G1_STAGEB;
        const uint32_t aT = st;
        const uint32_t bT = st + G_TILEB;

        #pragma unroll
        for (int kk = 0; kk < GBK; kk += 16) {
            uint32_t bf[16];
            #pragma unroll
            for (int nt2 = 0; nt2 < 4; nt2++) {
                const int n  = warp_n * 64 + nt2 * 16 + (lane & 7) + ((lane >> 4) << 3);
                const int kc = kk + (((lane >> 3) & 1) << 3);
                ldm_x4(&bf[nt2 * 4], bT + n * G_ROWB + kc * 2);
            }
            uint32_t af[16];
            {
                const int rbase = warp_m * 64 + (lane & 15);
                const int kc    = kk + ((lane >> 4) << 3);
                #pragma unroll
                for (int mt = 0; mt < 4; mt++)
                    ldm_x4(&af[mt * 4], aT + (rbase + mt * 16) * G_ROWB + kc * 2);
            }
            #pragma unroll
            for (int mt = 0; mt < 4; mt++)
                #pragma unroll
                for (int nt = 0; nt < 8; nt++) {
                    const int bi = (nt >> 1) * 4 + (nt & 1) * 2;
                    mma_fp16(acc[mt][nt], &af[mt * 4], bf[bi], bf[bi + 1]);
                }
        }
    }

    if (mat < 2) {
        float* C = mat ? Ck : Cq;
        #pragma unroll
        for (int mt = 0; mt < 4; mt++) {
            const int row0 = bm + warp_m * 64 + mt * 16 + (lane >> 2);
            #pragma unroll
            for (int nt = 0; nt < 8; nt++) {
                const int col = bn + warp_n * 64 + nt * 8 + ((lane & 3) << 1);
                const float b0 = bias[col], b1 = bias[col + 1];
                float2 v0 = { acc[mt][nt][0] + b0, acc[mt][nt][1] + b1 };
                float2 v1 = { acc[mt][nt][2] + b0, acc[mt][nt][3] + b1 };
                *(float2*)&C[(size_t)row0 * DIM + col]       = v0;
                *(float2*)&C[(size_t)(row0 + 8) * DIM + col] = v1;
            }
        }
    } else {
        #pragma unroll
        for (int mt = 0; mt < 4; mt++) {
            const int row0 = bm + warp_m * 64 + mt * 16 + (lane >> 2);
            #pragma unroll
            for (int nt = 0; nt < 8; nt++) {
                const int col = bn + warp_n * 64 + nt * 8 + ((lane & 3) << 1);
                const float b0 = bias[col], b1 = bias[col + 1];
                __half2 v0 = __floats2half2_rn(acc[mt][nt][0] + b0, acc[mt][nt][1] + b1);
                __half2 v1 = __floats2half2_rn(acc[mt][nt][2] + b0, acc[mt][nt][3] + b1);
                *(uint32_t*)&Cv[(size_t)row0 * DIM + col]       = *(uint32_t*)&v0;
                *(uint32_t*)&Cv[(size_t)(row0 + 8) * DIM + col] = *(uint32_t*)&v1;
            }
        }
    }
}

// ---------------------------------------------------------------------------
// Wo GEMM: verified round-12 128x128 2-stage
// ---------------------------------------------------------------------------
__global__ __launch_bounds__(256)
void gemm1_kernel(const __half* __restrict__ A,
                  const __half* __restrict__ B,
                  const float* __restrict__ bias,
                  float* __restrict__ C) {
    extern __shared__ char smem[];
    const uint32_t sbase = smem_u32(smem);
    const int tid  = threadIdx.x;
    const int wid  = tid >> 5;
    const int lane = tid & 31;
    const int bm   = blockIdx.y * GBM;
    const int bn   = blockIdx.x * GBN;
    const int warp_m = wid & 1;
    const int warp_n = wid >> 1;

    const __half* basep[2] = { A + (size_t)bm * DIM, B + (size_t)bn * DIM };
    const int cp_row[2] = { tid >> 2, (tid + 256) >> 2 };
    const int cp_c4     = tid & 3;

    auto copy_chunk = [&](int c, uint32_t stage) {
        #pragma unroll
        for (int t = 0; t < 2; t++) {
            #pragma unroll
            for (int half = 0; half < 2; half++) {
                const int row = cp_row[half];
                const __half* g = basep[t] + (size_t)row * DIM + c * GBK + cp_c4 * 8;
                CP_ASYNC16(stage + t * G_TILEB + row * G_ROWB + cp_c4 * 16, g);
            }
        }
    };

    float acc[4][4][4] = {};
    copy_chunk(0, sbase);
    CP_COMMIT();

    for (int c = 0; c < G_NC; c++) {
        __syncthreads();
        if (c + 1 < G_NC) {
            copy_chunk(c + 1, sbase + ((c + 1) & 1) * G1_STAGEB);
            CP_COMMIT();
            CP_WAIT1();
        } else {
            CP_WAIT0();
        }
        __syncthreads();

        const uint32_t st = sbase + (c & 1) * G1_STAGEB;
        const uint32_t aT = st;
        const uint32_t bT = st + G_TILEB;

        #pragma unroll
        for (int kk = 0; kk < GBK; kk += 16) {
            uint32_t bf[8];
            #pragma unroll
            for (int nt2 = 0; nt2 < 2; nt2++) {
                const int n  = warp_n * 32 + nt2 * 16 + (lane & 7) + ((lane >> 4) << 3);
                const int kc = kk + (((lane >> 3) & 1) << 3);
                ldm_x4(&bf[nt2 * 4], bT + n * G_ROWB + kc * 2);
            }
            uint32_t af[16];
            {
                const int rbase = warp_m * 64 + (lane & 15);
                const int kc    = kk + ((lane >> 4) << 3);
                #pragma unroll
                for (int mt = 0; mt < 4; mt++)
                    ldm_x4(&af[mt * 4], aT + (rbase + mt * 16) * G_ROWB + kc * 2);
            }
            #pragma unroll
            for (int mt = 0; mt < 4; mt++)
                #pragma unroll
                for (int nt = 0; nt < 4; nt++) {
                    const int bi = (nt >> 1) * 4 + (nt & 1) * 2;
                    mma_fp16(acc[mt][nt], &af[mt * 4], bf[bi], bf[bi + 1]);
                }
        }
    }

    #pragma unroll
    for (int mt = 0; mt < 4; mt++) {
        const int row0 = bm + warp_m * 64 + mt * 16 + (lane >> 2);
        #pragma unroll
        for (int nt = 0; nt < 4; nt++) {
            const int col = bn + warp_n * 32 + nt * 8 + ((lane & 3) << 1);
            const float b0 = bias[col], b1 = bias[col + 1];
            float2 v0 = { acc[mt][nt][0] + b0, acc[mt][nt][1] + b1 };
            float2 v1 = { acc[mt][nt][2] + b0, acc[mt][nt][3] + b1 };
            *(float2*)&C[(size_t)row0 * DIM + col]       = v0;
            *(float2*)&C[(size_t)(row0 + 8) * DIM + col] = v1;
        }
    }
}

// ---------------------------------------------------------------------------
// Fused RMSNorm + RoPE: verified round-12 scalar version
// ---------------------------------------------------------------------------
__global__ void rmsnorm_rope_kernel(const float* __restrict__ Xq,
                                    const float* __restrict__ Xk,
                                    const float* __restrict__ gqv,
                                    const float* __restrict__ gkv,
                                    const float* __restrict__ fc,
                                    const float* __restrict__ fs,
                                    __half* __restrict__ Oq,
                                    __half* __restrict__ Ok) {
    const int s = blockIdx.x;
    const int which = blockIdx.y;
    const float* X = which ? Xk : Xq;
    const float* g = which ? gkv : gqv;
    __half* O = which ? Ok : Oq;

    __shared__ float buf[DIM];
    __shared__ float red[8];
    __shared__ float s_scale;

    const float* row = X + (size_t)s * DIM;

    float ss = 0.f;
    for (int i = threadIdx.x; i < DIM; i += blockDim.x) {
        float v = row[i];
        buf[i] = v;
        ss += v * v;
    }
    #pragma unroll
    for (int o = 16; o > 0; o >>= 1) ss += __shfl_xor_sync(0xFFFFFFFFu, ss, o);
    if ((threadIdx.x & 31) == 0) red[threadIdx.x >> 5] = ss;
    __syncthreads();
    if (threadIdx.x == 0) {
        float t = 0.f;
        #pragma unroll
        for (int w = 0; w < 8; w++) t += red[w];
        s_scale = rsqrtf(t / (float)DIM + 1e-6f);
    }
    __syncthreads();
    const float scale = s_scale;

    const float* fcs = fc + (size_t)s * HDIM;
    const float* fss = fs + (size_t)s * HDIM;

    for (int i = threadIdx.x; i < DIM; i += blockDim.x) {
        int j = i & (HDIM - 1);
        float v = buf[i] * scale * g[i];
        float out;
        if (j < HDIM / 2) {
            float other = buf[i + HDIM / 2] * scale * g[i + HDIM / 2];
            out = v * fcs[j] - other * fss[j];
        } else {
            float other = buf[i - HDIM / 2] * scale * g[i - HDIM / 2];
            out = v * fcs[j] + other * fss[j];
        }
        O[(size_t)s * DIM + i] = __float2half(out);
    }
}

// ---------------------------------------------------------------------------
// Flash attention (round-14/15 verified, 276us): register softmax + split-K +
// f16x2 exp + l-via-ones-mma + skip-rescale vote. NO fused combine.
// ---------------------------------------------------------------------------
#define A_PITCH 272
#define Q_TILEB (128 * A_PITCH)
#define KV_TILEB (64 * A_PITCH)
#define OFF_KV  Q_TILEB
#define ATT_SMEM (OFF_KV + 4 * KV_TILEB)   // 104448

__global__ __launch_bounds__(128)
void attn_mma_kernel(const __half* __restrict__ Q_g,
                     const __half* __restrict__ K_g,
                     const __half* __restrict__ V_g,
                     float* __restrict__ U,
                     float* __restrict__ Sm,
                     float* __restrict__ Sl) {
    extern __shared__ char smem[];
    const uint32_t sb = smem_u32(smem);
    const int tid  = threadIdx.x;
    const int wid  = tid >> 5;
    const int lane = tid & 31;
    const int h    = blockIdx.y;
    const int q0   = blockIdx.x * 128;
    const int split = blockIdx.z;
    const int kt0    = split == 0 ? 0 : (split == 1 ? 22 : 43);
    const int ntiles = split == 0 ? 22 : 21;

    const uint32_t sQ = sb;

    #pragma unroll
    for (int i = 0; i < 16; i++) {
        int cid = i * 128 + tid;
        int row = cid >> 4, c = cid & 15;
        const __half* gp = Q_g + (size_t)(q0 + row) * DIM + h * HDIM + c * 8;
        CP_ASYNC16(sQ + row * A_PITCH + c * 16, gp);
    }
    const __half* kvsrc[2] = { K_g, V_g };
    auto load_stage = [&](int kt, int s) {
        uint32_t stb = sb + OFF_KV + s * 2 * KV_TILEB;
        #pragma unroll
        for (int i = 0; i < 16; i++) {
            int cid = i * 128 + tid;
            int tile = cid >> 10, row = (cid >> 4) & 63, c = cid & 15;
            const __half* gp = kvsrc[tile] + (size_t)(kt * 64 + row) * DIM + h * HDIM + c * 8;
            CP_ASYNC16(stb + tile * KV_TILEB + row * A_PITCH + c * 16, gp);
        }
    };
    load_stage(kt0, 0);
    CP_COMMIT();
    load_stage(kt0 + 1, 1);
    CP_COMMIT();

    float m00 = -1e30f, m01 = -1e30f, m10 = -1e30f, m11 = -1e30f;
    float oacc[2][16][4] = {};
    float lacc[2][4] = {};

    const int rb = wid * 32 + (lane & 15);

    for (int t = 0; t < ntiles; t++) {
        if (t < ntiles - 1) CP_WAIT1(); else CP_WAIT0();
        __syncthreads();
        const uint32_t st = sb + OFF_KV + (t & 1) * 2 * KV_TILEB;
        const uint32_t sK = st;
        const uint32_t sV = st + KV_TILEB;

        float sacc[2][8][4] = {};
        #pragma unroll
        for (int kk = 0; kk < 8; kk++) {
            uint32_t aq0[4], aq1[4];
            const int kc = kk * 16 + ((lane >> 4) << 3);
            ldm_x4(aq0, sQ + rb * A_PITCH + kc * 2);
            ldm_x4(aq1, sQ + (rb + 16) * A_PITCH + kc * 2);
            const int kc2 = kk * 16 + (((lane >> 3) & 1) << 3);
            #pragma unroll
            for (int half = 0; half < 2; half++) {
                uint32_t bk[8];
                const int nr = half * 32 + (lane & 7) + ((lane >> 4) << 3);
                ldm_x4(bk,     sK + nr * A_PITCH + kc2 * 2);
                ldm_x4(bk + 4, sK + (nr + 16) * A_PITCH + kc2 * 2);
                #pragma unroll
                for (int j = 0; j < 4; j++) {
                    mma_fp16(sacc[0][half * 4 + j], aq0, bk[j * 2], bk[j * 2 + 1]);
                    mma_fp16(sacc[1][half * 4 + j], aq1, bk[j * 2], bk[j * 2 + 1]);
                }
            }
        }

        uint32_t pA[2][8], pB[2][8];
        float a00, a01, a10, a11;
        #pragma unroll
        for (int mt = 0; mt < 2; mt++) {
            float mx0 = -1e30f, mx1 = -1e30f;
            #pragma unroll
            for (int nt = 0; nt < 8; nt++) {
                mx0 = fmaxf(mx0, fmaxf(sacc[mt][nt][0], sacc[mt][nt][1]));
                mx1 = fmaxf(mx1, fmaxf(sacc[mt][nt][2], sacc[mt][nt][3]));
            }
            mx0 = fmaxf(mx0, __shfl_xor_sync(0xFFFFFFFFu, mx0, 1));
            mx0 = fmaxf(mx0, __shfl_xor_sync(0xFFFFFFFFu, mx0, 2));
            mx1 = fmaxf(mx1, __shfl_xor_sync(0xFFFFFFFFu, mx1, 1));
            mx1 = fmaxf(mx1, __shfl_xor_sync(0xFFFFFFFFu, mx1, 2));
            float& m0r = mt ? m10 : m00;
            float& m1r = mt ? m11 : m01;
            const float mn0 = fmaxf(m0r, mx0);
            const float mn1 = fmaxf(m1r, mx1);
            const float a0 = ex2f((m0r - mn0) * K2C);
            const float a1 = ex2f((m1r - mn1) * K2C);
            m0r = mn0; m1r = mn1;
            const float mnK0 = mn0 * K2C;
            const float mnK1 = mn1 * K2C;
            #pragma unroll
            for (int nt = 0; nt < 8; nt++) {
                float e0 = fmaf(sacc[mt][nt][0], K2C, -mnK0);
                float e1 = fmaf(sacc[mt][nt][1], K2C, -mnK0);
                float e2 = fmaf(sacc[mt][nt][2], K2C, -mnK1);
                float e3 = fmaf(sacc[mt][nt][3], K2C, -mnK1);
                __half2 hA = __floats2half2_rn(e0, e1);
                __half2 hB = __floats2half2_rn(e2, e3);
                pA[mt][nt] = ex2_h2(*(uint32_t*)&hA);
                pB[mt][nt] = ex2_h2(*(uint32_t*)&hB);
            }
            if (mt) { a10 = a0; a11 = a1; } else { a00 = a0; a01 = a1; }
        }

        const bool noscale = (a00 == 1.f) & (a01 == 1.f) & (a10 == 1.f) & (a11 == 1.f);
        if (!__all_sync(0xFFFFFFFFu, noscale)) {
            #pragma unroll
            for (int nt = 0; nt < 16; nt++) {
                oacc[0][nt][0] *= a00; oacc[0][nt][1] *= a00;
                oacc[0][nt][2] *= a01; oacc[0][nt][3] *= a01;
                oacc[1][nt][0] *= a10; oacc[1][nt][1] *= a10;
                oacc[1][nt][2] *= a11; oacc[1][nt][3] *= a11;
            }
            lacc[0][0] *= a00; lacc[0][1] *= a00;
            lacc[0][2] *= a01; lacc[0][3] *= a01;
            lacc[1][0] *= a10; lacc[1][1] *= a10;
            lacc[1][2] *= a11; lacc[1][3] *= a11;
        }

        #pragma unroll
        for (int kk = 0; kk < 4; kk++) {
            uint32_t ap0[4] = { pA[0][2 * kk], pB[0][2 * kk],
                                pA[0][2 * kk + 1], pB[0][2 * kk + 1] };
            uint32_t ap1[4] = { pA[1][2 * kk], pB[1][2 * kk],
                                pA[1][2 * kk + 1], pB[1][2 * kk + 1] };
            const int vr = kk * 16 + (lane & 7) + (((lane >> 3) & 1) << 3);
            #pragma unroll
            for (int q = 0; q < 4; q++) {
                uint32_t bv[8];
                const int vc = q * 32 + ((lane >> 4) << 3);
                ldm_x4_t(bv,     sV + vr * A_PITCH + vc * 2);
                ldm_x4_t(bv + 4, sV + vr * A_PITCH + (vc + 16) * 2);
                #pragma unroll
                for (int j = 0; j < 4; j++) {
                    mma_fp16(oacc[0][q * 4 + j], ap0, bv[j * 2], bv[j * 2 + 1]);
                    mma_fp16(oacc[1][q * 4 + j], ap1, bv[j * 2], bv[j * 2 + 1]);
                }
            }
            mma_fp16(lacc[0], ap0, ONES_H2, ONES_H2);
            mma_fp16(lacc[1], ap1, ONES_H2, ONES_H2);
        }
        __syncthreads();

        if (t + 2 < ntiles) {
            load_stage(kt0 + t + 2, t & 1);
            CP_COMMIT();
        }
    }

    #pragma unroll
    for (int mt = 0; mt < 2; mt++) {
        const int r = wid * 32 + mt * 16 + (lane >> 2);
        const int row0 = q0 + r, row1 = q0 + r + 8;
        const float m0 = mt ? m10 : m00;
        const float m1 = mt ? m11 : m01;
        if ((lane & 3) == 0) {
            const int sbp = (split * NHEAD + h) * S_LEN;
            Sm[sbp + row0] = m0; Sl[sbp + row0] = lacc[mt][0];
            Sm[sbp + row1] = m1; Sl[sbp + row1] = lacc[mt][2];
        }
        float* Ub = U + (size_t)split * S_LEN * DIM;
        const size_t gr0 = (size_t)row0 * DIM;
        const size_t gr1 = (size_t)row1 * DIM;
        #pragma unroll
        for (int nt = 0; nt < 16; nt++) {
            const int col = h * HDIM + nt * 8 + ((lane & 3) << 1);
            float2 u0 = { oacc[mt][nt][0], oacc[mt][nt][1] };
            float2 u1 = { oacc[mt][nt][2], oacc[mt][nt][3] };
            *(float2*)&Ub[gr0 + col] = u0;
            *(float2*)&Ub[gr1 + col] = u1;
        }
    }
}

// ---------------------------------------------------------------------------
// split-K combine (verified rounds 10-15)
// ---------------------------------------------------------------------------
__global__ void combine_kernel(const float* __restrict__ U,
                               const float* __restrict__ Sm,
                               const float* __restrict__ Sl,
                               __half* __restrict__ A) {
    int idx = blockIdx.x * blockDim.x + threadIdx.x;
    int e = idx * 4;
    if (e >= S_LEN * DIM) return;
    const int row = e / DIM;
    const int col = e % DIM;
    const int h = col >> 7;

    const int s0 = (0 * NHEAD + h) * S_LEN + row;
    const int s1 = (1 * NHEAD + h) * S_LEN + row;
    const int s2 = (2 * NHEAD + h) * S_LEN + row;
    const float m0 = Sm[s0], m1 = Sm[s1], m2 = Sm[s2];
    const float M = fmaxf(m0, fmaxf(m1, m2));
    const float w0 = ex2f((m0 - M) * K2C);
    const float w1 = ex2f((m1 - M) * K2C);
    const float w2 = ex2f((m2 - M) * K2C);
    const float inv = 1.f / (Sl[s0] * w0 + Sl[s1] * w1 + Sl[s2] * w2);

    const size_t stride = (size_t)S_LEN * DIM;
    float4 u0 = *(const float4*)&U[e];
    float4 u1 = *(const float4*)&U[stride + e];
    float4 u2 = *(const float4*)&U[2 * stride + e];
    float o0 = (u0.x * w0 + u1.x * w1 + u2.x * w2) * inv;
    float o1 = (u0.y * w0 + u1.y * w1 + u2.y * w2) * inv;
    float o2 = (u0.z * w0 + u1.z * w1 + u2.z * w2) * inv;
    float o3 = (u0.w * w0 + u1.w * w1 + u2.w * w2) * inv;
    __half2 p0 = __floats2half2_rn(o0, o1);
    __half2 p1 = __floats2half2_rn(o2, o3);
    uint2 o = { *(uint32_t*)&p0, *(uint32_t*)&p1 };
    *(uint2*)&A[e] = o;
}

// ---------------------------------------------------------------------------
extern "C" void kernel_launch(void* const* d_in, const int* in_sizes, int n_in,
                              void* d_out, int out_size) {
    const float* x   = (const float*)d_in[0];
    const float* fc  = (const float*)d_in[1];
    const float* fs  = (const float*)d_in[2];
    const float* Wq  = (const float*)d_in[3];
    const float* bq  = (const float*)d_in[4];
    const float* Wk  = (const float*)d_in[5];
    const float* bk  = (const float*)d_in[6];
    const float* Wv  = (const float*)d_in[7];
    const float* bv  = (const float*)d_in[8];
    const float* Wo  = (const float*)d_in[9];
    const float* bo  = (const float*)d_in[10];
    const float* gq  = (const float*)d_in[11];
    const float* gk  = (const float*)d_in[12];
    float* out = (float*)d_out;

    float *dQ, *dK, *dU, *dSm, *dSl;
    cudaGetSymbolAddress((void**)&dQ, g_Q);
    cudaGetSymbolAddress((void**)&dK, g_K);
    cudaGetSymbolAddress((void**)&dU, g_U);
    cudaGetSymbolAddress((void**)&dSm, g_Sm);
    cudaGetSymbolAddress((void**)&dSl, g_Sl);
    __half *xf, *af, *qf, *kf, *vf, *wqkv, *wof;
    cudaGetSymbolAddress((void**)&xf, g_xf);
    cudaGetSymbolAddress((void**)&af, g_Af);
    cudaGetSymbolAddress((void**)&qf, g_Qf);
    cudaGetSymbolAddress((void**)&kf, g_Kf);
    cudaGetSymbolAddress((void**)&vf, g_Vf);
    cudaGetSymbolAddress((void**)&wqkv, g_Wqkv);
    cudaGetSymbolAddress((void**)&wof, g_Wof);

    convert_all_kernel<<<2048, 256>>>(x, Wq, Wk, Wv, Wo, xf, wqkv, wof);

    cudaFuncSetAttribute(gemm_qkv_kernel, cudaFuncAttributeMaxDynamicSharedMemorySize, G1_SMEM);
    cudaFuncSetAttribute(gemm1_kernel, cudaFuncAttributeMaxDynamicSharedMemorySize, G1_SMEM);

    dim3 gqkv(3 * DIM / GBN, S_LEN / GBM);
    gemm_qkv_kernel<<<gqkv, 128, G1_SMEM>>>(xf, wqkv, bq, bk, bv, dQ, dK, vf);

    dim3 rgrid(S_LEN, 2);
    rmsnorm_rope_kernel<<<rgrid, 256>>>(dQ, dK, gq, gk, fc, fs, qf, kf);

    cudaFuncSetAttribute(attn_mma_kernel, cudaFuncAttributeMaxDynamicSharedMemorySize, ATT_SMEM);
    dim3 agrid(S_LEN / 128, NHEAD, KSPLIT);
    attn_mma_kernel<<<agrid, 128, ATT_SMEM>>>(qf, kf, vf, dU, dSm, dSl);

    combine_kernel<<<(S_LEN * DIM / 4 + 255) / 256, 256>>>(dU, dSm, dSl, af);

    dim3 ggrid(DIM / GBN, S_LEN / GBM);
    gemm1_kernel<<<ggrid, 256, G1_SMEM>>>(af, wof, bo, out);
}